// round 1
// baseline (speedup 1.0000x reference)
#include <cuda_runtime.h>
#include <math.h>

// PositionalEmbedding: out[n,j] = (x[n]==0 ? 0 : W[x[n],j]) + pe(n+1, j)
// pe(pos, j) = cos(pos * w_{j/2})        for even j
//            = sin(pos * w_{(j+1)/2})    for odd  j
// with w_m = powf(1e-4f, m/512)  (matches jnp.power(1e-4, expo) on XLA:GPU / libdevice)
//
// Numerics strategy: reproduce the reference's fp32 computation path exactly:
// fp32 w via powf, fp32 product pos*w, libdevice sincosf of that fp32 angle.
// Each sincosf serves two output columns (sin at j=2m-1, cos at j=2m); the
// remaining cos for the float4's first slot comes from the previous lane via
// shfl (lane 0 computes its own via cosf).

#define DHID 1024
#define THREADS 256   // one thread per float4 (4 columns) of a row
#define ROWS_PER_CTA 32

__global__ __launch_bounds__(THREADS)
void pe_embed_kernel(const int* __restrict__ x,
                     const float4* __restrict__ W4,
                     float4* __restrict__ out4,
                     int N)
{
    const int t    = threadIdx.x;       // column group: j = 4t .. 4t+3
    const int lane = t & 31;
    const long long row0 = (long long)blockIdx.x * ROWS_PER_CTA;
    if (row0 >= N) return;

    // Angle-index weights (hoisted: powf is expensive, amortize over rows).
    // exponents m/512 are exact fp32 (power-of-two divisor), identical to the
    // reference's (j or j+1)/1024.
    const float base   = 1.0f / 10000.0f;         // == jnp.asarray(1.0/10000.0, f32)
    const float inv512 = 1.0f / 512.0f;
    const float w0 = powf(base, (float)(2 * t    ) * inv512);  // for col j=4t   (cos), lane-0 fallback
    const float w1 = powf(base, (float)(2 * t + 1) * inv512);  // cols 4t+1 (sin), 4t+2 (cos)
    const float w2 = powf(base, (float)(2 * t + 2) * inv512);  // col  4t+3 (sin); cos goes to lane+1

    const long long rend = (row0 + ROWS_PER_CTA < (long long)N) ? row0 + ROWS_PER_CTA : (long long)N;

    for (long long n = row0; n < rend; ++n) {
        const float pos = (float)(n + 1);

        float sA, cA, sB, cB;
        sincosf(pos * w1, &sA, &cA);   // a_{2t+1}
        sincosf(pos * w2, &sB, &cB);   // a_{2t+2}

        // cos(a_{2t}) == cB of lane-1 neighbor (its a_{2(t-1)+2} = a_{2t})
        float c0 = __shfl_up_sync(0xFFFFFFFFu, cB, 1);
        if (lane == 0) c0 = cosf(pos * w0);

        const int idx = __ldg(&x[n]);
        float4 e;
        if (idx == 0) {
            e = make_float4(0.f, 0.f, 0.f, 0.f);   // padding_idx row is zero
        } else {
            e = __ldg(&W4[(long long)idx * (DHID / 4) + t]);
        }

        float4 o;
        o.x = e.x + c0;   // j = 4t     : cos(a_{2t})
        o.y = e.y + sA;   // j = 4t + 1 : sin(a_{2t+1})
        o.z = e.z + cA;   // j = 4t + 2 : cos(a_{2t+1})
        o.w = e.w + sB;   // j = 4t + 3 : sin(a_{2t+2})
        out4[n * (DHID / 4) + t] = o;
    }
}

extern "C" void kernel_launch(void* const* d_in, const int* in_sizes, int n_in,
                              void* d_out, int out_size)
{
    const int*    x  = (const int*)d_in[0];       // int32 [N]
    const float*  W  = (const float*)d_in[1];     // f32 [V, 1024]
    float*        out = (float*)d_out;            // f32 [N, 1024]
    const int N = in_sizes[0];

    const int grid = (N + ROWS_PER_CTA - 1) / ROWS_PER_CTA;
    pe_embed_kernel<<<grid, THREADS>>>(x, (const float4*)W, (float4*)out, N);
}

// round 3
// speedup vs baseline: 1.0855x; 1.0855x over previous
#include <cuda_runtime.h>
#include <math.h>

// out[n,j] = (x[n]==0 ? 0 : W[x[n],j]) + pe(n+1, j)
// pe(pos, j): even j -> cos(pos*w_{j/2}), odd j -> sin(pos*w_{(j+1)/2}),
// w_m = powf(1e-4f, m/512).
//
// Per thread (t in [0,256)) owns columns j=4t..4t+3, needing angles
//   th0 = pos*w_{2t} (cos), th1 = pos*w_{2t+1} (sin & cos), th2 = pos*w_{2t+2} (sin).
//
// Two paths, chosen per-warp (w monotone in t => warp-uniform, no divergence):
//  EXACT   (max angle in this CTA's row block > T): sincosf on fl(pos*w), matching
//          the reference's fp32 rounding path bit-for-bit in the angle.
//  ROTATE  (all angles small): maintain (sin,cos) state for th0/th1/th2 and advance
//          by a per-row rotation with precomputed (sin w, cos w). 12 FMA/row replaces
//          2 sincosf. Divergence vs reference bounded by the reference's own
//          fl(pos*w) rounding noise (~theta*1.2e-7 <= 3.6e-4 at theta=T), RMS << 1e-4.

#define DHID 1024
#define THREADS 256
#define ROWS_PER_CTA 32
#define ANGLE_T 3000.0f

__global__ __launch_bounds__(THREADS)
void pe_embed_kernel(const int* __restrict__ x,
                     const float4* __restrict__ W4,
                     float4* __restrict__ out4,
                     int N)
{
    const int t    = threadIdx.x;
    const int lane = t & 31;
    const long long row0 = (long long)blockIdx.x * ROWS_PER_CTA;
    if (row0 >= N) return;
    const long long rend = (row0 + ROWS_PER_CTA < (long long)N) ? row0 + ROWS_PER_CTA
                                                                : (long long)N;

    const float base   = 1.0f / 10000.0f;
    const float inv512 = 1.0f / 512.0f;
    const float w0 = powf(base, (float)(2 * t    ) * inv512);
    const float w1 = powf(base, (float)(2 * t + 1) * inv512);
    const float w2 = powf(base, (float)(2 * t + 2) * inv512);

    // warp-uniform path decision: largest angle in warp is lane 0's w0
    const float wmax = __shfl_sync(0xFFFFFFFFu, w0, 0);
    const bool exact = ((float)rend * wmax) > ANGLE_T;

    if (exact) {
        // ---- exact path: bit-match reference's fl(pos*w) + libdevice sincos ----
        int idx = __ldg(&x[row0]);
        for (long long n = row0; n < rend; ++n) {
            const float pos = (float)(n + 1);
            float sA, cA, sB, cB;
            sincosf(pos * w1, &sA, &cA);
            sincosf(pos * w2, &sB, &cB);
            float c0 = __shfl_up_sync(0xFFFFFFFFu, cB, 1);
            if (lane == 0) c0 = cosf(pos * w0);

            float4 e = make_float4(0.f, 0.f, 0.f, 0.f);
            if (idx != 0) e = __ldg(&W4[(long long)idx * (DHID / 4) + t]);
            if (n + 1 < rend) idx = __ldg(&x[n + 1]);

            float4 o;
            o.x = e.x + c0;
            o.y = e.y + sA;
            o.z = e.z + cA;
            o.w = e.w + sB;
            __stcs(&out4[n * (DHID / 4) + t], o);   // evict-first: keep W in L2
        }
    } else {
        // ---- rotation path: 3 (sin,cos) states advanced by w per row ----
        const float pos0 = (float)(row0 + 1);
        float s0, c0, s1, c1, s2, c2;
        sincosf(pos0 * w0, &s0, &c0);
        sincosf(pos0 * w1, &s1, &c1);
        sincosf(pos0 * w2, &s2, &c2);
        float sw0, cw0, sw1, cw1, sw2, cw2;
        sincosf(w0, &sw0, &cw0);
        sincosf(w1, &sw1, &cw1);
        sincosf(w2, &sw2, &cw2);

        int idx = __ldg(&x[row0]);
        for (long long n = row0; n < rend; ++n) {
            float4 e = make_float4(0.f, 0.f, 0.f, 0.f);
            if (idx != 0) e = __ldg(&W4[(long long)idx * (DHID / 4) + t]);
            if (n + 1 < rend) idx = __ldg(&x[n + 1]);

            float4 o;
            o.x = e.x + c0;
            o.y = e.y + s1;
            o.z = e.z + c1;
            o.w = e.w + s2;
            __stcs(&out4[n * (DHID / 4) + t], o);

            // rotate states by their per-row step
            float ns0 = fmaf(s0, cw0,  c0 * sw0);
            float nc0 = fmaf(c0, cw0, -s0 * sw0);
            float ns1 = fmaf(s1, cw1,  c1 * sw1);
            float nc1 = fmaf(c1, cw1, -s1 * sw1);
            float ns2 = fmaf(s2, cw2,  c2 * sw2);
            float nc2 = fmaf(c2, cw2, -s2 * sw2);
            s0 = ns0; c0 = nc0;
            s1 = ns1; c1 = nc1;
            s2 = ns2; c2 = nc2;
        }
    }
}

extern "C" void kernel_launch(void* const* d_in, const int* in_sizes, int n_in,
                              void* d_out, int out_size)
{
    const int*   x   = (const int*)d_in[0];    // int32 [N]
    const float* W   = (const float*)d_in[1];  // f32 [V,1024]
    float*       out = (float*)d_out;          // f32 [N,1024]
    const int N = in_sizes[0];

    const int grid = (N + ROWS_PER_CTA - 1) / ROWS_PER_CTA;
    pe_embed_kernel<<<grid, THREADS>>>(x, (const float4*)W, (float4*)out, N);
}

// round 4
// speedup vs baseline: 1.1203x; 1.0320x over previous
#include <cuda_runtime.h>
#include <math.h>

// out[n,j] = (x[n]==0 ? 0 : W[x[n],j]) + pe(n+1, j)
// pe(pos,j): even j -> cos(pos*w_{j/2}); odd j -> sin(pos*w_{(j+1)/2}); w_m = 1e-4^(m/512).
// Thread t owns cols 4t..4t+3 -> angles th0=pos*w_{2t} (cos), th1=pos*w_{2t+1} (sin,cos),
// th2=pos*w_{2t+2} (sin).
//
// Warp-uniform path split (w monotone in t):
//   EXACT : sincosf(fl(pos*w)) — matches reference rounding path.
//   ROTATE: (sin,cos) states advanced by per-row rotation (12 FMA/row).
// R3: 4-row unroll — 4 independent 16B gathers in flight per thread (MLP 1 -> 4),
// next-chunk index prefetch, evict-first stores to protect W's L2 residency.

#define DHID 1024
#define THREADS 256
#define ROWS_PER_CTA 32
#define UNROLL 4
#define ANGLE_T 3000.0f

__global__ __launch_bounds__(THREADS)
void pe_embed_kernel(const int* __restrict__ x,
                     const float4* __restrict__ W4,
                     float4* __restrict__ out4,
                     int N)
{
    const int t    = threadIdx.x;
    const int lane = t & 31;
    const long long row0 = (long long)blockIdx.x * ROWS_PER_CTA;
    if (row0 >= N) return;
    const long long rend = (row0 + ROWS_PER_CTA < (long long)N) ? row0 + ROWS_PER_CTA
                                                                : (long long)N;

    const float base   = 1.0f / 10000.0f;
    const float inv512 = 1.0f / 512.0f;
    const float w0 = powf(base, (float)(2 * t    ) * inv512);
    const float w1 = powf(base, (float)(2 * t + 1) * inv512);
    const float w2 = powf(base, (float)(2 * t + 2) * inv512);

    const float wmax = __shfl_sync(0xFFFFFFFFu, w0, 0);
    const bool exact = ((float)rend * wmax) > ANGLE_T;

    const bool full = ((rend - row0) % UNROLL) == 0;   // true for all non-tail CTAs

    if (exact) {
        if (full) {
            int idx[UNROLL];
            #pragma unroll
            for (int k = 0; k < UNROLL; ++k) idx[k] = __ldg(&x[row0 + k]);

            for (long long n = row0; n < rend; n += UNROLL) {
                // issue 4 independent gathers
                float4 e[UNROLL];
                #pragma unroll
                for (int k = 0; k < UNROLL; ++k) {
                    e[k] = make_float4(0.f, 0.f, 0.f, 0.f);
                    if (idx[k] != 0)
                        e[k] = __ldg(&W4[(long long)idx[k] * (DHID / 4) + t]);
                }
                // prefetch next chunk's indices
                if (n + UNROLL < rend) {
                    #pragma unroll
                    for (int k = 0; k < UNROLL; ++k) idx[k] = __ldg(&x[n + UNROLL + k]);
                }
                // compute pe + store (overlaps with gather latency of later e[k])
                #pragma unroll
                for (int k = 0; k < UNROLL; ++k) {
                    const float pos = (float)(n + k + 1);
                    float sA, cA, sB, cB;
                    sincosf(pos * w1, &sA, &cA);
                    sincosf(pos * w2, &sB, &cB);
                    float c0 = __shfl_up_sync(0xFFFFFFFFu, cB, 1);
                    if (lane == 0) c0 = cosf(pos * w0);
                    float4 o;
                    o.x = e[k].x + c0;
                    o.y = e[k].y + sA;
                    o.z = e[k].z + cA;
                    o.w = e[k].w + sB;
                    __stcs(&out4[(n + k) * (DHID / 4) + t], o);
                }
            }
        } else {
            for (long long n = row0; n < rend; ++n) {
                const float pos = (float)(n + 1);
                float sA, cA, sB, cB;
                sincosf(pos * w1, &sA, &cA);
                sincosf(pos * w2, &sB, &cB);
                float c0 = __shfl_up_sync(0xFFFFFFFFu, cB, 1);
                if (lane == 0) c0 = cosf(pos * w0);
                const int idx = __ldg(&x[n]);
                float4 e = make_float4(0.f, 0.f, 0.f, 0.f);
                if (idx != 0) e = __ldg(&W4[(long long)idx * (DHID / 4) + t]);
                float4 o;
                o.x = e.x + c0; o.y = e.y + sA; o.z = e.z + cA; o.w = e.w + sB;
                __stcs(&out4[n * (DHID / 4) + t], o);
            }
        }
    } else {
        // rotation path: 3 (sin,cos) states, advanced by w per row
        const float pos0 = (float)(row0 + 1);
        float s0, c0, s1, c1, s2, c2;
        sincosf(pos0 * w0, &s0, &c0);
        sincosf(pos0 * w1, &s1, &c1);
        sincosf(pos0 * w2, &s2, &c2);
        float sw0, cw0, sw1, cw1, sw2, cw2;
        sincosf(w0, &sw0, &cw0);
        sincosf(w1, &sw1, &cw1);
        sincosf(w2, &sw2, &cw2);

        if (full) {
            int idx[UNROLL];
            #pragma unroll
            for (int k = 0; k < UNROLL; ++k) idx[k] = __ldg(&x[row0 + k]);

            for (long long n = row0; n < rend; n += UNROLL) {
                float4 e[UNROLL];
                #pragma unroll
                for (int k = 0; k < UNROLL; ++k) {
                    e[k] = make_float4(0.f, 0.f, 0.f, 0.f);
                    if (idx[k] != 0)
                        e[k] = __ldg(&W4[(long long)idx[k] * (DHID / 4) + t]);
                }
                if (n + UNROLL < rend) {
                    #pragma unroll
                    for (int k = 0; k < UNROLL; ++k) idx[k] = __ldg(&x[n + UNROLL + k]);
                }
                #pragma unroll
                for (int k = 0; k < UNROLL; ++k) {
                    float4 o;
                    o.x = e[k].x + c0;
                    o.y = e[k].y + s1;
                    o.z = e[k].z + c1;
                    o.w = e[k].w + s2;
                    __stcs(&out4[(n + k) * (DHID / 4) + t], o);

                    float ns0 = fmaf(s0, cw0,  c0 * sw0);
                    float nc0 = fmaf(c0, cw0, -s0 * sw0);
                    float ns1 = fmaf(s1, cw1,  c1 * sw1);
                    float nc1 = fmaf(c1, cw1, -s1 * sw1);
                    float ns2 = fmaf(s2, cw2,  c2 * sw2);
                    float nc2 = fmaf(c2, cw2, -s2 * sw2);
                    s0 = ns0; c0 = nc0;
                    s1 = ns1; c1 = nc1;
                    s2 = ns2; c2 = nc2;
                }
            }
        } else {
            for (long long n = row0; n < rend; ++n) {
                const int idx = __ldg(&x[n]);
                float4 e = make_float4(0.f, 0.f, 0.f, 0.f);
                if (idx != 0) e = __ldg(&W4[(long long)idx * (DHID / 4) + t]);
                float4 o;
                o.x = e.x + c0; o.y = e.y + s1; o.z = e.z + c1; o.w = e.w + s2;
                __stcs(&out4[n * (DHID / 4) + t], o);

                float ns0 = fmaf(s0, cw0,  c0 * sw0);
                float nc0 = fmaf(c0, cw0, -s0 * sw0);
                float ns1 = fmaf(s1, cw1,  c1 * sw1);
                float nc1 = fmaf(c1, cw1, -s1 * sw1);
                float ns2 = fmaf(s2, cw2,  c2 * sw2);
                float nc2 = fmaf(c2, cw2, -s2 * sw2);
                s0 = ns0; c0 = nc0;
                s1 = ns1; c1 = nc1;
                s2 = ns2; c2 = nc2;
            }
        }
    }
}

extern "C" void kernel_launch(void* const* d_in, const int* in_sizes, int n_in,
                              void* d_out, int out_size)
{
    const int*   x   = (const int*)d_in[0];    // int32 [N]
    const float* W   = (const float*)d_in[1];  // f32 [V,1024]
    float*       out = (float*)d_out;          // f32 [N,1024]
    const int N = in_sizes[0];

    const int grid = (N + ROWS_PER_CTA - 1) / ROWS_PER_CTA;
    pe_embed_kernel<<<grid, THREADS>>>(x, (const float4*)W, (float4*)out, N);
}